// round 9
// baseline (speedup 1.0000x reference)
#include <cuda_runtime.h>
#include <math.h>

#define Bsz 4096
#define Tsz 64
#define Fsz 37
#define TB 4          // batch elements per CTA
#define NP 12         // TB * 3 timesteps
#define NT 128        // threads per CTA (one per hidden unit)
#define FDIM 150      // lin width
#define LINP 152      // padded lin stride (608B rows, 16B aligned)
#define FP4 38        // ceil(FDIM/4) quad-f groups (padded with zeros)
#define KP4 32        // H/4 quad-k groups
#define GATES 512
#define H 128

typedef unsigned long long ull;

// ---- global scratch: quad-f packed LSTM weights, gate-interleaved ----
// g_wk4[(fq*4 + c)*H + j] = (w[4fq],w[4fq+1] | w[4fq+2],w[4fq+3]) gate c, unit j
__device__ ulonglong2 g_wk4[FP4 * 4 * H];   // 311 KB
__device__ ulonglong2 g_wr4[KP4 * 4 * H];   // 262 KB

// shared memory layout (floats)
#define OFF_FEAT 0        // 12*37 = 444 (aliased by head buffers later)
#define OFF_T1M1 448      // 12*16 = 192
#define OFF_S1   640      // 12*32 = 384
#define OFF_LIN  1024     // 3*4*152 = 1824 (byte 4096, 16B aligned)
#define OFF_H    2848     // 4*128 = 512    (byte 11392, 16B aligned)
#define SMEM_FLOATS 3360  // 13440 bytes

struct Params {
    const float *feature;
    const float *w_m1, *b_m1, *w_m2, *b_m2;
    const float *w_t1, *b_t1, *w_t2, *b_t2;
    const float *w_s1, *b_s1, *w_s2, *b_s2;
    const float *w_lk, *w_lr, *b_l;
    const float *w_p1, *b_p1, *w_p2, *b_p2, *w_p3, *b_p3, *w_p4, *b_p4, *w_p5, *b_p5;
    float *out;
};

__device__ __forceinline__ float lrelu(float x) { return x >= 0.f ? x : 0.2f * x; }
__device__ __forceinline__ float sigm(float x) { return 1.f / (1.f + __expf(-x)); }

__device__ __forceinline__ ull pack2(float lo, float hi) {
    ull v;
    asm("mov.b64 %0, {%1, %2};" : "=l"(v) : "f"(lo), "f"(hi));
    return v;
}
__device__ __forceinline__ void unpack2(float &lo, float &hi, ull v) {
    asm("mov.b64 {%0, %1}, %2;" : "=f"(lo), "=f"(hi) : "l"(v));
}
__device__ __forceinline__ void ffma2(ull &acc, ull a, ull b) {
    asm("fma.rn.f32x2 %0, %1, %2, %0;" : "+l"(acc) : "l"(a), "l"(b));
}

// ---- pre-kernel: repack w_lk/w_lr into gate-interleaved quad-f streams ----
__global__ void repack_kernel(const float *__restrict__ wlk,
                              const float *__restrict__ wlr) {
    int i = blockIdx.x * 256 + threadIdx.x;
    if (i < FP4 * 4 * H) {
        int fq = i / (4 * H), r = i % (4 * H);
        int c = r / H, j = r % H;
        float w[4];
        #pragma unroll
        for (int q = 0; q < 4; ++q) {
            int f = 4 * fq + q;
            w[q] = (f < FDIM) ? wlk[f * GATES + c * H + j] : 0.f;
        }
        g_wk4[i] = make_ulonglong2(pack2(w[0], w[1]), pack2(w[2], w[3]));
    }
    if (i < KP4 * 4 * H) {
        int kq = i / (4 * H), r = i % (4 * H);
        int c = r / H, j = r % H;
        float w[4];
        #pragma unroll
        for (int q = 0; q < 4; ++q)
            w[q] = wlr[(4 * kq + q) * GATES + c * H + j];
        g_wr4[i] = make_ulonglong2(pack2(w[0], w[1]), pack2(w[2], w[3]));
    }
}

// lin batch-major: [t][b][f], f contiguous, stride LINP
#define LIDX(t, f, b) (((t) * TB + (b)) * LINP + (f))

__global__ void __launch_bounds__(NT) lstm_fused_kernel(Params P) {
    __shared__ __align__(16) float sm[SMEM_FLOATS];
    const int tid = threadIdx.x;
    const int bg0 = blockIdx.x * TB;

    float *feat = sm + OFF_FEAT;
    float *t1m1 = sm + OFF_T1M1;
    float *S1   = sm + OFF_S1;
    float *linB = sm + OFF_LIN;
    float *hB   = sm + OFF_H;     // [b][k], rows 512B

    // ---- load feature rows t=0..2 for 4 batch elems; zero lin pad cols ----
    for (int i = tid; i < NP * Fsz; i += NT) {
        int p = i / Fsz, f = i % Fsz;
        int b = p / 3, t = p % 3;
        feat[p * Fsz + f] =
            P.feature[(size_t)(bg0 + b) * Tsz * Fsz + (size_t)t * Fsz + f];
    }
    if (tid < NP) {
        linB[tid * LINP + 150] = 0.f;
        linB[tid * LINP + 151] = 0.f;
    }
    __syncthreads();

    // ---- pass1: M1 (q<8) and T1 (q>=8), per (b,t) pair p ----
    for (int i = tid; i < NP * 16; i += NT) {
        int p = i >> 4, q = i & 15;
        const float *fr = feat + p * Fsz;
        float acc;
        if (q < 8) {
            acc = P.b_m1[q];
            #pragma unroll
            for (int f = 0; f < 3; ++f) acc += fr[33 + f] * P.w_m1[f * 8 + q];
            acc = lrelu(acc);
        } else {
            int j = q - 8;
            acc = P.b_t1[j];
            #pragma unroll
            for (int f = 0; f < Fsz; ++f) acc += fr[f] * P.w_t1[f * 8 + j];
            acc = lrelu(acc);
            acc = fabsf(acc);
        }
        t1m1[i] = acc;
    }
    __syncthreads();

    // ---- pass2: M -> lin[0:16], Tsk -> lin[16:32], Psk -> lin[32:48] ----
    for (int i = tid; i < NP * 32; i += NT) {
        int p = i >> 5, q = i & 31;
        int b = p / 3, t = p % 3;
        if (q < 16) {
            float acc = P.b_m2[q];
            #pragma unroll
            for (int k = 0; k < 8; ++k) acc += t1m1[p * 16 + k] * P.w_m2[k * 16 + q];
            linB[LIDX(t, q, b)] = lrelu(acc);
        } else {
            int j = q - 16;
            float acc = P.b_t2[j];
            #pragma unroll
            for (int k = 0; k < 8; ++k) acc += t1m1[p * 16 + 8 + k] * P.w_t2[k * 16 + j];
            float v = (acc >= 0.f) ? acc : -0.2f * acc;  // abs(lrelu)
            linB[LIDX(t, 16 + j, b)] = v;
            linB[LIDX(t, 32 + j, b)] = log1pf(v);
        }
    }
    // Pa -> lin[48], feature copy -> lin[113:150]
    for (int i = tid; i < NP * 38; i += NT) {
        int p = i / 38, q = i % 38;
        int b = p / 3, t = p % 3;
        if (q == 0) linB[LIDX(t, 48, b)] = log1pf(feat[p * Fsz + 31]);
        else        linB[LIDX(t, 113 + (q - 1), b)] = feat[p * Fsz + (q - 1)];
    }
    __syncthreads();

    // ---- pass3: S1 = lrelu(s_in @ w_s1 + b_s1) ----
    for (int i = tid; i < NP * 32; i += NT) {
        int p = i >> 5, j = i & 31;
        int b = p / 3, t = p % 3;
        float acc = P.b_s1[j];
        for (int f = 0; f < 49; ++f) acc += linB[LIDX(t, f, b)] * P.w_s1[f * 32 + j];
        const float *fr = feat + p * Fsz;
        #pragma unroll
        for (int e = 0; e < 6; ++e) acc += fr[27 + e] * P.w_s1[(49 + e) * 32 + j];
        #pragma unroll
        for (int e = 0; e < 3; ++e) acc += fr[33 + e] * P.w_s1[(55 + e) * 32 + j];
        S1[p * 32 + j] = lrelu(acc);
    }
    __syncthreads();

    // ---- pass4: S -> lin[49:113] ----
    for (int i = tid; i < NP * 64; i += NT) {
        int p = i >> 6, j = i & 63;
        int b = p / 3, t = p % 3;
        float acc = P.b_s2[j];
        #pragma unroll
        for (int k = 0; k < 32; ++k) acc += S1[p * 32 + k] * P.w_s2[k * 64 + j];
        linB[LIDX(t, 49 + j, b)] = lrelu(acc);
    }
    __syncthreads();

    // ---- LSTM: 3 timesteps. Thread tid owns hidden unit j for all 4 gates
    // and all 4 batches. f32x2 lanes hold (even-f, odd-f) partial sums;
    // gate-interleaved quad-f weights: one pointer + immediate offsets.
    {
        const int j = tid;
        const float bi0 = P.b_l[j], bi1 = P.b_l[j + H];
        const float bi2 = P.b_l[j + 2 * H], bi3 = P.b_l[j + 3 * H];
        float cres[TB];
        #pragma unroll
        for (int b = 0; b < TB; ++b) cres[b] = 0.f;

        for (int t = 0; t < 3; ++t) {
            ull acc0[TB], acc1[TB], acc2[TB], acc3[TB];
            #pragma unroll
            for (int b = 0; b < TB; ++b) {
                acc0[b] = pack2(bi0, 0.f);
                acc1[b] = pack2(bi1, 0.f);
                acc2[b] = pack2(bi2, 0.f);
                acc3[b] = pack2(bi3, 0.f);
            }

            // input GEMM: z += lin_t @ w_lk   (38 quad-f groups)
            {
                const ulonglong2 *wp = g_wk4 + j;          // +c*H imm offsets
                const float *lp = linB + t * TB * LINP;    // +b*LINP imm offsets
                #pragma unroll 2
                for (int fq = 0; fq < FP4; ++fq) {
                    ulonglong2 w0 = __ldg(wp + 0 * H);
                    ulonglong2 w1 = __ldg(wp + 1 * H);
                    ulonglong2 w2 = __ldg(wp + 2 * H);
                    ulonglong2 w3 = __ldg(wp + 3 * H);
                    ulonglong2 a[TB];
                    #pragma unroll
                    for (int b = 0; b < TB; ++b)
                        a[b] = *(const ulonglong2 *)(lp + b * LINP);
                    #pragma unroll
                    for (int b = 0; b < TB; ++b) {
                        ffma2(acc0[b], a[b].x, w0.x);
                        ffma2(acc1[b], a[b].x, w1.x);
                        ffma2(acc2[b], a[b].x, w2.x);
                        ffma2(acc3[b], a[b].x, w3.x);
                    }
                    #pragma unroll
                    for (int b = 0; b < TB; ++b) {
                        ffma2(acc0[b], a[b].y, w0.y);
                        ffma2(acc1[b], a[b].y, w1.y);
                        ffma2(acc2[b], a[b].y, w2.y);
                        ffma2(acc3[b], a[b].y, w3.y);
                    }
                    wp += 4 * H;
                    lp += 4;
                }
            }
            // recurrent GEMM: z += h @ w_lr   (32 quad-k groups; h==0 at t=0)
            if (t > 0) {
                const ulonglong2 *wp = g_wr4 + j;
                const float *hp = hB;
                #pragma unroll 2
                for (int kq = 0; kq < KP4; ++kq) {
                    ulonglong2 w0 = __ldg(wp + 0 * H);
                    ulonglong2 w1 = __ldg(wp + 1 * H);
                    ulonglong2 w2 = __ldg(wp + 2 * H);
                    ulonglong2 w3 = __ldg(wp + 3 * H);
                    ulonglong2 a[TB];
                    #pragma unroll
                    for (int b = 0; b < TB; ++b)
                        a[b] = *(const ulonglong2 *)(hp + b * H);
                    #pragma unroll
                    for (int b = 0; b < TB; ++b) {
                        ffma2(acc0[b], a[b].x, w0.x);
                        ffma2(acc1[b], a[b].x, w1.x);
                        ffma2(acc2[b], a[b].x, w2.x);
                        ffma2(acc3[b], a[b].x, w3.x);
                    }
                    #pragma unroll
                    for (int b = 0; b < TB; ++b) {
                        ffma2(acc0[b], a[b].y, w0.y);
                        ffma2(acc1[b], a[b].y, w1.y);
                        ffma2(acc2[b], a[b].y, w2.y);
                        ffma2(acc3[b], a[b].y, w3.y);
                    }
                    wp += 4 * H;
                    hp += 4;
                }
            }

            // all reads of hB (this t) must finish before overwrite
            __syncthreads();

            // lane-add + gates + state update, fully in registers
            #pragma unroll
            for (int b = 0; b < TB; ++b) {
                float zi_l, zi_h, zf_l, zf_h, zg_l, zg_h, zo_l, zo_h;
                unpack2(zi_l, zi_h, acc0[b]);
                unpack2(zf_l, zf_h, acc1[b]);
                unpack2(zg_l, zg_h, acc2[b]);
                unpack2(zo_l, zo_h, acc3[b]);
                float zi = zi_l + zi_h, zf = zf_l + zf_h;
                float zg = zg_l + zg_h, zo = zo_l + zo_h;
                float cv = sigm(zf) * cres[b] + sigm(zi) * lrelu(zg);
                cres[b] = cv;
                hB[b * H + j] = sigm(zo) * lrelu(cv);
            }
            __syncthreads();
        }
    }

    // ---- head at t=2 (buffers alias dead front-end smem) ----
    float *d1 = sm;        // 4*64 = 256
    float *d2 = sm + 256;  // 4*32
    float *d3 = sm + 384;  // 4*16
    float *d4 = sm + 448;  // 4*8
    float *d5 = sm + 480;  // 4*3

    for (int i = tid; i < TB * 64; i += NT) {
        int b = i >> 6, j = i & 63;
        float acc = P.b_p1[j];
        for (int k = 0; k < H; ++k) acc += hB[b * H + k] * P.w_p1[k * 64 + j];
        d1[i] = lrelu(acc);
    }
    __syncthreads();
    for (int i = tid; i < TB * 32; i += NT) {
        int b = i >> 5, j = i & 31;
        float acc = P.b_p2[j];
        #pragma unroll
        for (int k = 0; k < 64; ++k) acc += d1[b * 64 + k] * P.w_p2[k * 32 + j];
        d2[i] = lrelu(acc);
    }
    __syncthreads();
    for (int i = tid; i < TB * 16; i += NT) {
        int b = i >> 4, j = i & 15;
        float acc = P.b_p3[j];
        #pragma unroll
        for (int k = 0; k < 32; ++k) acc += d2[b * 32 + k] * P.w_p3[k * 16 + j];
        d3[i] = lrelu(acc);
    }
    __syncthreads();
    for (int i = tid; i < TB * 8; i += NT) {
        int b = i >> 3, j = i & 7;
        float acc = P.b_p4[j];
        #pragma unroll
        for (int k = 0; k < 16; ++k) acc += d3[b * 16 + k] * P.w_p4[k * 8 + j];
        d4[i] = lrelu(acc);
    }
    __syncthreads();
    for (int i = tid; i < TB * 3; i += NT) {
        int b = i / 3, j = i % 3;
        float acc = P.b_p5[j];
        #pragma unroll
        for (int k = 0; k < 8; ++k) acc += d4[b * 8 + k] * P.w_p5[k * 3 + j];
        d5[i] = lrelu(acc);
    }
    __syncthreads();

    // ---- softmax + write both outputs ----
    if (tid < TB) {
        int b = tid;
        float l0 = d5[b * 3 + 0], l1 = d5[b * 3 + 1], l2 = d5[b * 3 + 2];
        float m = fmaxf(l0, fmaxf(l1, l2));
        float e0 = __expf(l0 - m), e1 = __expf(l1 - m), e2 = __expf(l2 - m);
        float inv = 1.f / (e0 + e1 + e2);
        float o0 = e0 * inv, o1 = e1 * inv, o2 = e2 * inv;
        size_t gb = (size_t)(bg0 + b);
        float *outp = P.out + gb * 3;
        outp[0] = o0; outp[1] = o1; outp[2] = o2;
        float *xp = P.out + (size_t)Bsz * 3 + gb * 13;
        const float *fsrc = P.feature + gb * Tsz * Fsz + 2 * Fsz + 27;
        #pragma unroll
        for (int q = 0; q < 10; ++q) xp[q] = fsrc[q];
        xp[10] = o0; xp[11] = o1; xp[12] = o2;
    }
}

extern "C" void kernel_launch(void *const *d_in, const int *in_sizes, int n_in,
                              void *d_out, int out_size) {
    Params P;
    P.feature = (const float *)d_in[0];
    P.w_m1 = (const float *)d_in[1];  P.b_m1 = (const float *)d_in[2];
    P.w_m2 = (const float *)d_in[3];  P.b_m2 = (const float *)d_in[4];
    P.w_t1 = (const float *)d_in[5];  P.b_t1 = (const float *)d_in[6];
    P.w_t2 = (const float *)d_in[7];  P.b_t2 = (const float *)d_in[8];
    P.w_s1 = (const float *)d_in[9];  P.b_s1 = (const float *)d_in[10];
    P.w_s2 = (const float *)d_in[11]; P.b_s2 = (const float *)d_in[12];
    P.w_lk = (const float *)d_in[13];
    P.w_lr = (const float *)d_in[14];
    P.b_l  = (const float *)d_in[15];
    P.w_p1 = (const float *)d_in[16]; P.b_p1 = (const float *)d_in[17];
    P.w_p2 = (const float *)d_in[18]; P.b_p2 = (const float *)d_in[19];
    P.w_p3 = (const float *)d_in[20]; P.b_p3 = (const float *)d_in[21];
    P.w_p4 = (const float *)d_in[22]; P.b_p4 = (const float *)d_in[23];
    P.w_p5 = (const float *)d_in[24]; P.b_p5 = (const float *)d_in[25];
    P.out = (float *)d_out;

    repack_kernel<<<(FP4 * 4 * H + 255) / 256, 256>>>(P.w_lk, P.w_lr);
    lstm_fused_kernel<<<Bsz / TB, NT>>>(P);
}

// round 10
// speedup vs baseline: 1.0283x; 1.0283x over previous
#include <cuda_runtime.h>
#include <math.h>

#define Bsz 4096
#define Tsz 64
#define Fsz 37
#define TB 8          // batch elements per CTA
#define NP 24         // TB * 3 timesteps
#define NT 128        // threads per CTA (one per hidden unit)
#define FDIM 150      // lin width
#define LINP 152      // padded lin stride (608B rows, 16B aligned)
#define FP4 38        // ceil(FDIM/4) quad-f groups (padded with zeros)
#define KP4 32        // H/4 quad-k groups
#define GATES 512
#define H 128

typedef unsigned long long ull;

// ---- global scratch: quad-f packed LSTM weights ----
__device__ ulonglong2 g_wk4[4 * FP4 * H];   // 311 KB
__device__ ulonglong2 g_wr4[4 * KP4 * H];   // 262 KB

// shared memory layout (floats)
#define OFF_FEAT 0        // 24*37 = 888 (aliased by head buffers later)
#define OFF_T1M1 888      // 24*16 = 384
#define OFF_S1   1272     // 24*32 = 768
#define OFF_LIN  2040     // 3*8*152 = 3648 (byte 8160, 16B aligned)
#define OFF_H    5688     // 8*128 = 1024   (byte 22752, 16B aligned)
#define SMEM_FLOATS 6712  // 26848 bytes

struct Params {
    const float *feature;
    const float *w_m1, *b_m1, *w_m2, *b_m2;
    const float *w_t1, *b_t1, *w_t2, *b_t2;
    const float *w_s1, *b_s1, *w_s2, *b_s2;
    const float *w_lk, *w_lr, *b_l;
    const float *w_p1, *b_p1, *w_p2, *b_p2, *w_p3, *b_p3, *w_p4, *b_p4, *w_p5, *b_p5;
    float *out;
};

__device__ __forceinline__ float lrelu(float x) { return x >= 0.f ? x : 0.2f * x; }
__device__ __forceinline__ float sigm(float x) { return 1.f / (1.f + __expf(-x)); }

__device__ __forceinline__ ull pack2(float lo, float hi) {
    ull v;
    asm("mov.b64 %0, {%1, %2};" : "=l"(v) : "f"(lo), "f"(hi));
    return v;
}
__device__ __forceinline__ void unpack2(float &lo, float &hi, ull v) {
    asm("mov.b64 {%0, %1}, %2;" : "=f"(lo), "=f"(hi) : "l"(v));
}
__device__ __forceinline__ void ffma2(ull &acc, ull a, ull b) {
    asm("fma.rn.f32x2 %0, %1, %2, %0;" : "+l"(acc) : "l"(a), "l"(b));
}

// ---- pre-kernel: repack w_lk/w_lr into quad-f streams ----
__global__ void repack_kernel(const float *__restrict__ wlk,
                              const float *__restrict__ wlr) {
    int i = blockIdx.x * 256 + threadIdx.x;
    if (i < 4 * FP4 * H) {
        int c = i / (FP4 * H), r = i % (FP4 * H);
        int fq = r / H, j = r % H;
        float w[4];
        #pragma unroll
        for (int q = 0; q < 4; ++q) {
            int f = 4 * fq + q;
            w[q] = (f < FDIM) ? wlk[f * GATES + c * H + j] : 0.f;
        }
        g_wk4[i] = make_ulonglong2(pack2(w[0], w[1]), pack2(w[2], w[3]));
    }
    if (i < 4 * KP4 * H) {
        int c = i / (KP4 * H), r = i % (KP4 * H);
        int kq = r / H, j = r % H;
        float w[4];
        #pragma unroll
        for (int q = 0; q < 4; ++q)
            w[q] = wlr[(4 * kq + q) * GATES + c * H + j];
        g_wr4[i] = make_ulonglong2(pack2(w[0], w[1]), pack2(w[2], w[3]));
    }
}

// lin batch-major: [t][b][f], f contiguous, stride LINP. row r = t*TB+b
#define LIDX(t, f, b) (((t) * TB + (b)) * LINP + (f))

__global__ void __launch_bounds__(NT, 4) lstm_fused_kernel(Params P) {
    __shared__ __align__(16) float sm[SMEM_FLOATS];
    const int tid = threadIdx.x;
    const int bg0 = blockIdx.x * TB;

    float *feat = sm + OFF_FEAT;
    float *t1m1 = sm + OFF_T1M1;
    float *S1   = sm + OFF_S1;
    float *linB = sm + OFF_LIN;
    float *hB   = sm + OFF_H;     // [b][k], rows 512B

    // ---- load feature rows t=0..2 for 8 batch elems; zero lin pad cols ----
    for (int i = tid; i < NP * Fsz; i += NT) {
        int p = i / Fsz, f = i % Fsz;
        int b = p / 3, t = p % 3;
        feat[p * Fsz + f] =
            P.feature[(size_t)(bg0 + b) * Tsz * Fsz + (size_t)t * Fsz + f];
    }
    if (tid < NP) {
        linB[tid * LINP + 150] = 0.f;
        linB[tid * LINP + 151] = 0.f;
    }
    __syncthreads();

    // ---- pass1: M1 (q<8) and T1 (q>=8), per (b,t) pair p ----
    for (int i = tid; i < NP * 16; i += NT) {
        int p = i >> 4, q = i & 15;
        const float *fr = feat + p * Fsz;
        float acc;
        if (q < 8) {
            acc = P.b_m1[q];
            #pragma unroll
            for (int f = 0; f < 3; ++f) acc += fr[33 + f] * P.w_m1[f * 8 + q];
            acc = lrelu(acc);
        } else {
            int j = q - 8;
            acc = P.b_t1[j];
            #pragma unroll
            for (int f = 0; f < Fsz; ++f) acc += fr[f] * P.w_t1[f * 8 + j];
            acc = lrelu(acc);
            acc = fabsf(acc);
        }
        t1m1[i] = acc;
    }
    __syncthreads();

    // ---- pass2: M -> lin[0:16], Tsk -> lin[16:32], Psk -> lin[32:48] ----
    for (int i = tid; i < NP * 32; i += NT) {
        int p = i >> 5, q = i & 31;
        int b = p / 3, t = p % 3;
        if (q < 16) {
            float acc = P.b_m2[q];
            #pragma unroll
            for (int k = 0; k < 8; ++k) acc += t1m1[p * 16 + k] * P.w_m2[k * 16 + q];
            linB[LIDX(t, q, b)] = lrelu(acc);
        } else {
            int j = q - 16;
            float acc = P.b_t2[j];
            #pragma unroll
            for (int k = 0; k < 8; ++k) acc += t1m1[p * 16 + 8 + k] * P.w_t2[k * 16 + j];
            float v = (acc >= 0.f) ? acc : -0.2f * acc;  // abs(lrelu)
            linB[LIDX(t, 16 + j, b)] = v;
            linB[LIDX(t, 32 + j, b)] = log1pf(v);
        }
    }
    // Pa -> lin[48], feature copy -> lin[113:150]
    for (int i = tid; i < NP * 38; i += NT) {
        int p = i / 38, q = i % 38;
        int b = p / 3, t = p % 3;
        if (q == 0) linB[LIDX(t, 48, b)] = log1pf(feat[p * Fsz + 31]);
        else        linB[LIDX(t, 113 + (q - 1), b)] = feat[p * Fsz + (q - 1)];
    }
    __syncthreads();

    // ---- pass3: S1 = lrelu(s_in @ w_s1 + b_s1), j-quad vectorized ----
    // thread owns (row r, 4 output cols). w loads: float4, coalesced.
    for (int i = tid; i < NP * 8; i += NT) {
        int r = i >> 3, jq = (i & 7) * 4;
        int t = r / TB, b = r % TB, p = b * 3 + t;
        float4 acc = *(const float4 *)(P.b_s1 + jq);
        const float *lp = linB + r * LINP;
        for (int k = 0; k < 49; ++k) {
            float s = lp[k];
            float4 w = *(const float4 *)(P.w_s1 + k * 32 + jq);
            acc.x += s * w.x; acc.y += s * w.y;
            acc.z += s * w.z; acc.w += s * w.w;
        }
        const float *fr = feat + p * Fsz;
        #pragma unroll
        for (int e = 0; e < 6; ++e) {
            float s = fr[27 + e];
            float4 w = *(const float4 *)(P.w_s1 + (49 + e) * 32 + jq);
            acc.x += s * w.x; acc.y += s * w.y;
            acc.z += s * w.z; acc.w += s * w.w;
        }
        #pragma unroll
        for (int e = 0; e < 3; ++e) {
            float s = fr[33 + e];
            float4 w = *(const float4 *)(P.w_s1 + (55 + e) * 32 + jq);
            acc.x += s * w.x; acc.y += s * w.y;
            acc.z += s * w.z; acc.w += s * w.w;
        }
        *(float4 *)(S1 + r * 32 + jq) =
            make_float4(lrelu(acc.x), lrelu(acc.y), lrelu(acc.z), lrelu(acc.w));
    }
    __syncthreads();

    // ---- pass4: S -> lin[49:113], j-quad vectorized ----
    for (int i = tid; i < NP * 16; i += NT) {
        int r = i >> 4, jq = (i & 15) * 4;
        int t = r / TB, b = r % TB;
        float4 acc = *(const float4 *)(P.b_s2 + jq);
        const float *sp = S1 + r * 32;
        #pragma unroll
        for (int k = 0; k < 32; ++k) {
            float s = sp[k];
            float4 w = *(const float4 *)(P.w_s2 + k * 64 + jq);
            acc.x += s * w.x; acc.y += s * w.y;
            acc.z += s * w.z; acc.w += s * w.w;
        }
        float *dst = linB + LIDX(t, 49 + jq, b);
        dst[0] = lrelu(acc.x); dst[1] = lrelu(acc.y);
        dst[2] = lrelu(acc.z); dst[3] = lrelu(acc.w);
    }
    __syncthreads();

    // ---- LSTM: 3 timesteps (unchanged R8 core) ----
    {
        const int j = tid;
        const ulonglong2 *wk0 = g_wk4 + 0 * FP4 * H + j;
        const ulonglong2 *wk1 = g_wk4 + 1 * FP4 * H + j;
        const ulonglong2 *wk2 = g_wk4 + 2 * FP4 * H + j;
        const ulonglong2 *wk3 = g_wk4 + 3 * FP4 * H + j;
        const ulonglong2 *wr0 = g_wr4 + 0 * KP4 * H + j;
        const ulonglong2 *wr1 = g_wr4 + 1 * KP4 * H + j;
        const ulonglong2 *wr2 = g_wr4 + 2 * KP4 * H + j;
        const ulonglong2 *wr3 = g_wr4 + 3 * KP4 * H + j;
        const float bi0 = P.b_l[j], bi1 = P.b_l[j + H];
        const float bi2 = P.b_l[j + 2 * H], bi3 = P.b_l[j + 3 * H];
        float cres[TB];
        #pragma unroll
        for (int b = 0; b < TB; ++b) cres[b] = 0.f;

        for (int t = 0; t < 3; ++t) {
            ull acc0[TB], acc1[TB], acc2[TB], acc3[TB];
            #pragma unroll
            for (int b = 0; b < TB; ++b) {
                acc0[b] = pack2(bi0, 0.f);
                acc1[b] = pack2(bi1, 0.f);
                acc2[b] = pack2(bi2, 0.f);
                acc3[b] = pack2(bi3, 0.f);
            }

            // input GEMM: z += lin_t @ w_lk   (38 quad-f groups)
            #pragma unroll 2
            for (int fq = 0; fq < FP4; ++fq) {
                ulonglong2 w0 = __ldg(wk0 + fq * H);
                ulonglong2 w1 = __ldg(wk1 + fq * H);
                ulonglong2 w2 = __ldg(wk2 + fq * H);
                ulonglong2 w3 = __ldg(wk3 + fq * H);
                ulonglong2 a[TB];
                #pragma unroll
                for (int b = 0; b < TB; ++b)
                    a[b] = *(const ulonglong2 *)(linB + LIDX(t, 4 * fq, b));
                #pragma unroll
                for (int b = 0; b < TB; ++b) {
                    ffma2(acc0[b], a[b].x, w0.x);
                    ffma2(acc1[b], a[b].x, w1.x);
                    ffma2(acc2[b], a[b].x, w2.x);
                    ffma2(acc3[b], a[b].x, w3.x);
                }
                #pragma unroll
                for (int b = 0; b < TB; ++b) {
                    ffma2(acc0[b], a[b].y, w0.y);
                    ffma2(acc1[b], a[b].y, w1.y);
                    ffma2(acc2[b], a[b].y, w2.y);
                    ffma2(acc3[b], a[b].y, w3.y);
                }
            }
            // recurrent GEMM: z += h @ w_lr   (32 quad-k groups; h==0 at t=0)
            if (t > 0) {
                #pragma unroll 2
                for (int kq = 0; kq < KP4; ++kq) {
                    ulonglong2 w0 = __ldg(wr0 + kq * H);
                    ulonglong2 w1 = __ldg(wr1 + kq * H);
                    ulonglong2 w2 = __ldg(wr2 + kq * H);
                    ulonglong2 w3 = __ldg(wr3 + kq * H);
                    ulonglong2 a[TB];
                    #pragma unroll
                    for (int b = 0; b < TB; ++b)
                        a[b] = *(const ulonglong2 *)(hB + b * H + 4 * kq);
                    #pragma unroll
                    for (int b = 0; b < TB; ++b) {
                        ffma2(acc0[b], a[b].x, w0.x);
                        ffma2(acc1[b], a[b].x, w1.x);
                        ffma2(acc2[b], a[b].x, w2.x);
                        ffma2(acc3[b], a[b].x, w3.x);
                    }
                    #pragma unroll
                    for (int b = 0; b < TB; ++b) {
                        ffma2(acc0[b], a[b].y, w0.y);
                        ffma2(acc1[b], a[b].y, w1.y);
                        ffma2(acc2[b], a[b].y, w2.y);
                        ffma2(acc3[b], a[b].y, w3.y);
                    }
                }
            }

            // all reads of hB (this t) must finish before overwrite
            __syncthreads();

            // lane-add + gates + state update, fully in registers
            #pragma unroll
            for (int b = 0; b < TB; ++b) {
                float zi_l, zi_h, zf_l, zf_h, zg_l, zg_h, zo_l, zo_h;
                unpack2(zi_l, zi_h, acc0[b]);
                unpack2(zf_l, zf_h, acc1[b]);
                unpack2(zg_l, zg_h, acc2[b]);
                unpack2(zo_l, zo_h, acc3[b]);
                float zi = zi_l + zi_h, zf = zf_l + zf_h;
                float zg = zg_l + zg_h, zo = zo_l + zo_h;
                float cv = sigm(zf) * cres[b] + sigm(zi) * lrelu(zg);
                cres[b] = cv;
                hB[b * H + j] = sigm(zo) * lrelu(cv);
            }
            __syncthreads();
        }
    }

    // ---- head at t=2 (buffers alias dead front-end smem) ----
    float *d1 = sm;        // 8*64 = 512
    float *d2 = sm + 512;  // 8*32
    float *d3 = sm + 768;  // 8*16
    float *d4 = sm + 896;  // 8*8
    float *d5 = sm + 960;  // 8*3

    // p1: d1 = lrelu(h @ w_p1 + b_p1), j-quad x k-quad vectorized
    for (int i = tid; i < TB * 16; i += NT) {
        int b = i >> 4, jq = (i & 15) * 4;
        float4 acc = *(const float4 *)(P.b_p1 + jq);
        const float4 *hp = (const float4 *)(hB + b * H);
        #pragma unroll 4
        for (int kq = 0; kq < 32; ++kq) {
            float4 h4 = hp[kq];
            float4 w0 = *(const float4 *)(P.w_p1 + (4 * kq + 0) * 64 + jq);
            float4 w1 = *(const float4 *)(P.w_p1 + (4 * kq + 1) * 64 + jq);
            float4 w2 = *(const float4 *)(P.w_p1 + (4 * kq + 2) * 64 + jq);
            float4 w3 = *(const float4 *)(P.w_p1 + (4 * kq + 3) * 64 + jq);
            acc.x += h4.x * w0.x + h4.y * w1.x + h4.z * w2.x + h4.w * w3.x;
            acc.y += h4.x * w0.y + h4.y * w1.y + h4.z * w2.y + h4.w * w3.y;
            acc.z += h4.x * w0.z + h4.y * w1.z + h4.z * w2.z + h4.w * w3.z;
            acc.w += h4.x * w0.w + h4.y * w1.w + h4.z * w2.w + h4.w * w3.w;
        }
        *(float4 *)(d1 + b * 64 + jq) =
            make_float4(lrelu(acc.x), lrelu(acc.y), lrelu(acc.z), lrelu(acc.w));
    }
    __syncthreads();

    // p2: d2 = lrelu(d1 @ w_p2 + b_p2), j-pair x k-quad vectorized
    for (int i = tid; i < TB * 16; i += NT) {
        int b = i >> 4, jp = (i & 15) * 2;
        float2 acc = make_float2(P.b_p2[jp], P.b_p2[jp + 1]);
        const float4 *dp = (const float4 *)(d1 + b * 64);
        #pragma unroll
        for (int kq = 0; kq < 16; ++kq) {
            float4 s4 = dp[kq];
            float2 w0 = *(const float2 *)(P.w_p2 + (4 * kq + 0) * 32 + jp);
            float2 w1 = *(const float2 *)(P.w_p2 + (4 * kq + 1) * 32 + jp);
            float2 w2 = *(const float2 *)(P.w_p2 + (4 * kq + 2) * 32 + jp);
            float2 w3 = *(const float2 *)(P.w_p2 + (4 * kq + 3) * 32 + jp);
            acc.x += s4.x * w0.x + s4.y * w1.x + s4.z * w2.x + s4.w * w3.x;
            acc.y += s4.x * w0.y + s4.y * w1.y + s4.z * w2.y + s4.w * w3.y;
        }
        d2[b * 32 + jp]     = lrelu(acc.x);
        d2[b * 32 + jp + 1] = lrelu(acc.y);
    }
    __syncthreads();

    for (int i = tid; i < TB * 16; i += NT) {
        int b = i >> 4, j = i & 15;
        float acc = P.b_p3[j];
        #pragma unroll
        for (int k = 0; k < 32; ++k) acc += d2[b * 32 + k] * P.w_p3[k * 16 + j];
        d3[i] = lrelu(acc);
    }
    __syncthreads();
    for (int i = tid; i < TB * 8; i += NT) {
        int b = i >> 3, j = i & 7;
        float acc = P.b_p4[j];
        #pragma unroll
        for (int k = 0; k < 16; ++k) acc += d3[b * 16 + k] * P.w_p4[k * 8 + j];
        d4[i] = lrelu(acc);
    }
    __syncthreads();
    for (int i = tid; i < TB * 3; i += NT) {
        int b = i / 3, j = i % 3;
        float acc = P.b_p5[j];
        #pragma unroll
        for (int k = 0; k < 8; ++k) acc += d4[b * 8 + k] * P.w_p5[k * 3 + j];
        d5[i] = lrelu(acc);
    }
    __syncthreads();

    // ---- softmax + write both outputs ----
    if (tid < TB) {
        int b = tid;
        float l0 = d5[b * 3 + 0], l1 = d5[b * 3 + 1], l2 = d5[b * 3 + 2];
        float m = fmaxf(l0, fmaxf(l1, l2));
        float e0 = __expf(l0 - m), e1 = __expf(l1 - m), e2 = __expf(l2 - m);
        float inv = 1.f / (e0 + e1 + e2);
        float o0 = e0 * inv, o1 = e1 * inv, o2 = e2 * inv;
        size_t gb = (size_t)(bg0 + b);
        float *outp = P.out + gb * 3;
        outp[0] = o0; outp[1] = o1; outp[2] = o2;
        float *xp = P.out + (size_t)Bsz * 3 + gb * 13;
        const float *fsrc = P.feature + gb * Tsz * Fsz + 2 * Fsz + 27;
        #pragma unroll
        for (int q = 0; q < 10; ++q) xp[q] = fsrc[q];
        xp[10] = o0; xp[11] = o1; xp[12] = o2;
    }
}

extern "C" void kernel_launch(void *const *d_in, const int *in_sizes, int n_in,
                              void *d_out, int out_size) {
    Params P;
    P.feature = (const float *)d_in[0];
    P.w_m1 = (const float *)d_in[1];  P.b_m1 = (const float *)d_in[2];
    P.w_m2 = (const float *)d_in[3];  P.b_m2 = (const float *)d_in[4];
    P.w_t1 = (const float *)d_in[5];  P.b_t1 = (const float *)d_in[6];
    P.w_t2 = (const float *)d_in[7];  P.b_t2 = (const float *)d_in[8];
    P.w_s1 = (const float *)d_in[9];  P.b_s1 = (const float *)d_in[10];
    P.w_s2 = (const float *)d_in[11]; P.b_s2 = (const float *)d_in[12];
    P.w_lk = (const float *)d_in[13];
    P.w_lr = (const float *)d_in[14];
    P.b_l  = (const float *)d_in[15];
    P.w_p1 = (const float *)d_in[16]; P.b_p1 = (const float *)d_in[17];
    P.w_p2 = (const float *)d_in[18]; P.b_p2 = (const float *)d_in[19];
    P.w_p3 = (const float *)d_in[20]; P.b_p3 = (const float *)d_in[21];
    P.w_p4 = (const float *)d_in[22]; P.b_p4 = (const float *)d_in[23];
    P.w_p5 = (const float *)d_in[24]; P.b_p5 = (const float *)d_in[25];
    P.out = (float *)d_out;

    repack_kernel<<<(4 * FP4 * H + 255) / 256, 256>>>(P.w_lk, P.w_lr);
    lstm_fused_kernel<<<Bsz / TB, NT>>>(P);
}

// round 12
// speedup vs baseline: 1.0573x; 1.0282x over previous
#include <cuda_runtime.h>
#include <math.h>

#define Bsz 4096
#define Tsz 64
#define Fsz 37
#define TB 8          // batch elements per CTA
#define NP 24         // TB * 3 timesteps
#define NT 128        // threads per CTA (one per hidden unit)
#define FDIM 150      // lin width
#define LINP 152      // padded lin stride (608B rows, 16B aligned)
#define FP4 38        // ceil(FDIM/4) quad-f groups (padded with zeros)
#define KP4 32        // H/4 quad-k groups
#define GATES 512
#define H 128

typedef unsigned long long ull;

// ---- global scratch: packed weights ----
__device__ ulonglong2 g_wk4[4 * FP4 * H];   // LSTM input, quad-f
__device__ ulonglong2 g_wr4[4 * KP4 * H];   // LSTM recurrent, quad-k
__device__ ull g_ws1[24 * 32];              // w_s1 k-pairs (k 0..47)
__device__ ull g_ws2[16 * 64];              // w_s2 k-pairs
__device__ ull g_wp1[64 * 64];              // w_p1 k-pairs
__device__ ull g_wp2[32 * 32];              // w_p2 k-pairs

// shared memory layout (floats)
#define OFF_FEAT 0        // 24*37 = 888 (aliased by head buffers later)
#define OFF_T1M1 888      // 24*16 = 384
#define OFF_S1   1272     // 24*32 = 768 (byte 5088, 8B aligned; rows 128B)
#define OFF_LIN  2040     // 3*8*152 = 3648 (byte 8160, 16B aligned)
#define OFF_H    5688     // 8*128 = 1024   (byte 22752, 16B aligned)
#define SMEM_FLOATS 6712  // 26848 bytes

struct Params {
    const float *feature;
    const float *w_m1, *b_m1, *w_m2, *b_m2;
    const float *w_t1, *b_t1, *w_t2, *b_t2;
    const float *w_s1, *b_s1, *w_s2, *b_s2;
    const float *w_lk, *w_lr, *b_l;
    const float *w_p1, *b_p1, *w_p2, *b_p2, *w_p3, *b_p3, *w_p4, *b_p4, *w_p5, *b_p5;
    float *out;
};

__device__ __forceinline__ float lrelu(float x) { return x >= 0.f ? x : 0.2f * x; }
__device__ __forceinline__ float sigm(float x) { return 1.f / (1.f + __expf(-x)); }

__device__ __forceinline__ ull pack2(float lo, float hi) {
    ull v;
    asm("mov.b64 %0, {%1, %2};" : "=l"(v) : "f"(lo), "f"(hi));
    return v;
}
__device__ __forceinline__ void unpack2(float &lo, float &hi, ull v) {
    asm("mov.b64 {%0, %1}, %2;" : "=f"(lo), "=f"(hi) : "l"(v));
}
__device__ __forceinline__ void ffma2(ull &acc, ull a, ull b) {
    asm("fma.rn.f32x2 %0, %1, %2, %0;" : "+l"(acc) : "l"(a), "l"(b));
}

// ---- pre-kernel: repack all GEMM weights into f32x2-pair streams ----
__global__ void repack_kernel(const float *__restrict__ wlk,
                              const float *__restrict__ wlr,
                              const float *__restrict__ ws1,
                              const float *__restrict__ ws2,
                              const float *__restrict__ wp1,
                              const float *__restrict__ wp2) {
    int i = blockIdx.x * 256 + threadIdx.x;
    if (i < 4 * FP4 * H) {
        int c = i / (FP4 * H), r = i % (FP4 * H);
        int fq = r / H, j = r % H;
        float w[4];
        #pragma unroll
        for (int q = 0; q < 4; ++q) {
            int f = 4 * fq + q;
            w[q] = (f < FDIM) ? wlk[f * GATES + c * H + j] : 0.f;
        }
        g_wk4[i] = make_ulonglong2(pack2(w[0], w[1]), pack2(w[2], w[3]));
    }
    if (i < 4 * KP4 * H) {
        int c = i / (KP4 * H), r = i % (KP4 * H);
        int kq = r / H, j = r % H;
        float w[4];
        #pragma unroll
        for (int q = 0; q < 4; ++q)
            w[q] = wlr[(4 * kq + q) * GATES + c * H + j];
        g_wr4[i] = make_ulonglong2(pack2(w[0], w[1]), pack2(w[2], w[3]));
    }
    if (i < 24 * 32) {
        int kp = i / 32, j = i % 32;
        g_ws1[i] = pack2(ws1[(2 * kp) * 32 + j], ws1[(2 * kp + 1) * 32 + j]);
    }
    if (i < 16 * 64) {
        int kp = i / 64, j = i % 64;
        g_ws2[i] = pack2(ws2[(2 * kp) * 64 + j], ws2[(2 * kp + 1) * 64 + j]);
    }
    if (i < 64 * 64) {
        int kp = i / 64, j = i % 64;
        g_wp1[i] = pack2(wp1[(2 * kp) * 64 + j], wp1[(2 * kp + 1) * 64 + j]);
    }
    if (i < 32 * 32) {
        int kp = i / 32, j = i % 32;
        g_wp2[i] = pack2(wp2[(2 * kp) * 32 + j], wp2[(2 * kp + 1) * 32 + j]);
    }
}

// lin batch-major: [t][b][f], f contiguous, stride LINP. row r = t*TB+b
#define LIDX(t, f, b) (((t) * TB + (b)) * LINP + (f))

__global__ void __launch_bounds__(NT, 4) lstm_fused_kernel(Params P) {
    __shared__ __align__(16) float sm[SMEM_FLOATS];
    const int tid = threadIdx.x;
    const int bg0 = blockIdx.x * TB;

    float *feat = sm + OFF_FEAT;
    float *t1m1 = sm + OFF_T1M1;
    float *S1   = sm + OFF_S1;
    float *linB = sm + OFF_LIN;
    float *hB   = sm + OFF_H;     // [b][k], rows 512B

    // ---- load feature rows t=0..2 for 8 batch elems; zero lin pad cols ----
    for (int i = tid; i < NP * Fsz; i += NT) {
        int p = i / Fsz, f = i % Fsz;
        int b = p / 3, t = p % 3;
        feat[p * Fsz + f] =
            P.feature[(size_t)(bg0 + b) * Tsz * Fsz + (size_t)t * Fsz + f];
    }
    if (tid < NP) {
        linB[tid * LINP + 150] = 0.f;
        linB[tid * LINP + 151] = 0.f;
    }
    __syncthreads();

    // ---- pass1: M1 (q<8) and T1 (q>=8), per (b,t) pair p ----
    for (int i = tid; i < NP * 16; i += NT) {
        int p = i >> 4, q = i & 15;
        const float *fr = feat + p * Fsz;
        float acc;
        if (q < 8) {
            acc = P.b_m1[q];
            #pragma unroll
            for (int f = 0; f < 3; ++f) acc += fr[33 + f] * P.w_m1[f * 8 + q];
            acc = lrelu(acc);
        } else {
            int j = q - 8;
            acc = P.b_t1[j];
            #pragma unroll
            for (int f = 0; f < Fsz; ++f) acc += fr[f] * P.w_t1[f * 8 + j];
            acc = lrelu(acc);
            acc = fabsf(acc);
        }
        t1m1[i] = acc;
    }
    __syncthreads();

    // ---- pass2: M -> lin[0:16], Tsk -> lin[16:32], Psk -> lin[32:48] ----
    for (int i = tid; i < NP * 32; i += NT) {
        int p = i >> 5, q = i & 31;
        int b = p / 3, t = p % 3;
        if (q < 16) {
            float acc = P.b_m2[q];
            #pragma unroll
            for (int k = 0; k < 8; ++k) acc += t1m1[p * 16 + k] * P.w_m2[k * 16 + q];
            linB[LIDX(t, q, b)] = lrelu(acc);
        } else {
            int j = q - 16;
            float acc = P.b_t2[j];
            #pragma unroll
            for (int k = 0; k < 8; ++k) acc += t1m1[p * 16 + 8 + k] * P.w_t2[k * 16 + j];
            float v = (acc >= 0.f) ? acc : -0.2f * acc;  // abs(lrelu)
            linB[LIDX(t, 16 + j, b)] = v;
            linB[LIDX(t, 32 + j, b)] = log1pf(v);
        }
    }
    // Pa -> lin[48], feature copy -> lin[113:150]
    for (int i = tid; i < NP * 38; i += NT) {
        int p = i / 38, q = i % 38;
        int b = p / 3, t = p % 3;
        if (q == 0) linB[LIDX(t, 48, b)] = log1pf(feat[p * Fsz + 31]);
        else        linB[LIDX(t, 113 + (q - 1), b)] = feat[p * Fsz + (q - 1)];
    }
    __syncthreads();

    // ---- pass3: S1 = lrelu(s_in @ w_s1 + b_s1), k-pair f32x2 ----
    for (int i = tid; i < NP * 32; i += NT) {
        int p = i >> 5, j = i & 31;
        int b = p / 3, t = p % 3;
        ull acc = pack2(P.b_s1[j], 0.f);
        const ull *lp2 = (const ull *)(linB + (t * TB + b) * LINP);
        const ull *wp = g_ws1 + j;
        #pragma unroll 4
        for (int kp = 0; kp < 24; ++kp)
            ffma2(acc, lp2[kp], wp[kp * 32]);
        float al, ah;
        unpack2(al, ah, acc);
        float accs = al + ah;
        accs += linB[(t * TB + b) * LINP + 48] * P.w_s1[48 * 32 + j];
        const float *fr = feat + p * Fsz;
        #pragma unroll
        for (int e = 0; e < 6; ++e) accs += fr[27 + e] * P.w_s1[(49 + e) * 32 + j];
        #pragma unroll
        for (int e = 0; e < 3; ++e) accs += fr[33 + e] * P.w_s1[(55 + e) * 32 + j];
        S1[p * 32 + j] = lrelu(accs);
    }
    __syncthreads();

    // ---- pass4: S -> lin[49:113], k-pair f32x2 ----
    for (int i = tid; i < NP * 64; i += NT) {
        int p = i >> 6, j = i & 63;
        int b = p / 3, t = p % 3;
        ull acc = pack2(P.b_s2[j], 0.f);
        const ull *sp = (const ull *)(S1 + p * 32);
        const ull *wp = g_ws2 + j;
        #pragma unroll 4
        for (int kp = 0; kp < 16; ++kp)
            ffma2(acc, sp[kp], wp[kp * 64]);
        float al, ah;
        unpack2(al, ah, acc);
        linB[LIDX(t, 49 + j, b)] = lrelu(al + ah);
    }
    __syncthreads();

    // ---- LSTM: 3 timesteps (unchanged R8 core) ----
    {
        const int j = tid;
        const ulonglong2 *wk0 = g_wk4 + 0 * FP4 * H + j;
        const ulonglong2 *wk1 = g_wk4 + 1 * FP4 * H + j;
        const ulonglong2 *wk2 = g_wk4 + 2 * FP4 * H + j;
        const ulonglong2 *wk3 = g_wk4 + 3 * FP4 * H + j;
        const ulonglong2 *wr0 = g_wr4 + 0 * KP4 * H + j;
        const ulonglong2 *wr1 = g_wr4 + 1 * KP4 * H + j;
        const ulonglong2 *wr2 = g_wr4 + 2 * KP4 * H + j;
        const ulonglong2 *wr3 = g_wr4 + 3 * KP4 * H + j;
        const float bi0 = P.b_l[j], bi1 = P.b_l[j + H];
        const float bi2 = P.b_l[j + 2 * H], bi3 = P.b_l[j + 3 * H];
        float cres[TB];
        #pragma unroll
        for (int b = 0; b < TB; ++b) cres[b] = 0.f;

        for (int t = 0; t < 3; ++t) {
            ull acc0[TB], acc1[TB], acc2[TB], acc3[TB];
            #pragma unroll
            for (int b = 0; b < TB; ++b) {
                acc0[b] = pack2(bi0, 0.f);
                acc1[b] = pack2(bi1, 0.f);
                acc2[b] = pack2(bi2, 0.f);
                acc3[b] = pack2(bi3, 0.f);
            }

            // input GEMM: z += lin_t @ w_lk   (38 quad-f groups)
            #pragma unroll 2
            for (int fq = 0; fq < FP4; ++fq) {
                ulonglong2 w0 = __ldg(wk0 + fq * H);
                ulonglong2 w1 = __ldg(wk1 + fq * H);
                ulonglong2 w2 = __ldg(wk2 + fq * H);
                ulonglong2 w3 = __ldg(wk3 + fq * H);
                ulonglong2 a[TB];
                #pragma unroll
                for (int b = 0; b < TB; ++b)
                    a[b] = *(const ulonglong2 *)(linB + LIDX(t, 4 * fq, b));
                #pragma unroll
                for (int b = 0; b < TB; ++b) {
                    ffma2(acc0[b], a[b].x, w0.x);
                    ffma2(acc1[b], a[b].x, w1.x);
                    ffma2(acc2[b], a[b].x, w2.x);
                    ffma2(acc3[b], a[b].x, w3.x);
                }
                #pragma unroll
                for (int b = 0; b < TB; ++b) {
                    ffma2(acc0[b], a[b].y, w0.y);
                    ffma2(acc1[b], a[b].y, w1.y);
                    ffma2(acc2[b], a[b].y, w2.y);
                    ffma2(acc3[b], a[b].y, w3.y);
                }
            }
            // recurrent GEMM: z += h @ w_lr   (32 quad-k groups; h==0 at t=0)
            if (t > 0) {
                #pragma unroll 2
                for (int kq = 0; kq < KP4; ++kq) {
                    ulonglong2 w0 = __ldg(wr0 + kq * H);
                    ulonglong2 w1 = __ldg(wr1 + kq * H);
                    ulonglong2 w2 = __ldg(wr2 + kq * H);
                    ulonglong2 w3 = __ldg(wr3 + kq * H);
                    ulonglong2 a[TB];
                    #pragma unroll
                    for (int b = 0; b < TB; ++b)
                        a[b] = *(const ulonglong2 *)(hB + b * H + 4 * kq);
                    #pragma unroll
                    for (int b = 0; b < TB; ++b) {
                        ffma2(acc0[b], a[b].x, w0.x);
                        ffma2(acc1[b], a[b].x, w1.x);
                        ffma2(acc2[b], a[b].x, w2.x);
                        ffma2(acc3[b], a[b].x, w3.x);
                    }
                    #pragma unroll
                    for (int b = 0; b < TB; ++b) {
                        ffma2(acc0[b], a[b].y, w0.y);
                        ffma2(acc1[b], a[b].y, w1.y);
                        ffma2(acc2[b], a[b].y, w2.y);
                        ffma2(acc3[b], a[b].y, w3.y);
                    }
                }
            }

            // all reads of hB (this t) must finish before overwrite
            __syncthreads();

            // lane-add + gates + state update, fully in registers
            #pragma unroll
            for (int b = 0; b < TB; ++b) {
                float zi_l, zi_h, zf_l, zf_h, zg_l, zg_h, zo_l, zo_h;
                unpack2(zi_l, zi_h, acc0[b]);
                unpack2(zf_l, zf_h, acc1[b]);
                unpack2(zg_l, zg_h, acc2[b]);
                unpack2(zo_l, zo_h, acc3[b]);
                float zi = zi_l + zi_h, zf = zf_l + zf_h;
                float zg = zg_l + zg_h, zo = zo_l + zo_h;
                float cv = sigm(zf) * cres[b] + sigm(zi) * lrelu(zg);
                cres[b] = cv;
                hB[b * H + j] = sigm(zo) * lrelu(cv);
            }
            __syncthreads();
        }
    }

    // ---- head at t=2 (buffers alias dead front-end smem) ----
    float *d1 = sm;        // 8*64 = 512
    float *d2 = sm + 512;  // 8*32
    float *d3 = sm + 768;  // 8*16
    float *d4 = sm + 896;  // 8*8
    float *d5 = sm + 960;  // 8*3

    // p1: d1 = lrelu(h @ w_p1 + b_p1), k-pair f32x2
    for (int i = tid; i < TB * 64; i += NT) {
        int b = i >> 6, j = i & 63;
        ull acc = pack2(P.b_p1[j], 0.f);
        const ull *hp = (const ull *)(hB + b * H);
        const ull *wp = g_wp1 + j;
        #pragma unroll 8
        for (int kp = 0; kp < 64; ++kp)
            ffma2(acc, hp[kp], wp[kp * 64]);
        float al, ah;
        unpack2(al, ah, acc);
        d1[i] = lrelu(al + ah);
    }
    __syncthreads();
    // p2: d2 = lrelu(d1 @ w_p2 + b_p2), k-pair f32x2
    for (int i = tid; i < TB * 32; i += NT) {
        int b = i >> 5, j = i & 31;
        ull acc = pack2(P.b_p2[j], 0.f);
        const ull *dp = (const ull *)(d1 + b * 64);
        const ull *wp = g_wp2 + j;
        #pragma unroll 4
        for (int kp = 0; kp < 32; ++kp)
            ffma2(acc, dp[kp], wp[kp * 32]);
        float al, ah;
        unpack2(al, ah, acc);
        d2[i] = lrelu(al + ah);
    }
    __syncthreads();
    for (int i = tid; i < TB * 16; i += NT) {
        int b = i >> 4, j = i & 15;
        float acc = P.b_p3[j];
        #pragma unroll
        for (int k = 0; k < 32; ++k) acc += d2[b * 32 + k] * P.w_p3[k * 16 + j];
        d3[i] = lrelu(acc);
    }
    __syncthreads();
    for (int i = tid; i < TB * 8; i += NT) {
        int b = i >> 3, j = i & 7;
        float acc = P.b_p4[j];
        #pragma unroll
        for (int k = 0; k < 16; ++k) acc += d3[b * 16 + k] * P.w_p4[k * 8 + j];
        d4[i] = lrelu(acc);
    }
    __syncthreads();
    for (int i = tid; i < TB * 3; i += NT) {
        int b = i / 3, j = i % 3;
        float acc = P.b_p5[j];
        #pragma unroll
        for (int k = 0; k < 8; ++k) acc += d4[b * 8 + k] * P.w_p5[k * 3 + j];
        d5[i] = lrelu(acc);
    }
    __syncthreads();

    // ---- softmax + write both outputs ----
    if (tid < TB) {
        int b = tid;
        float l0 = d5[b * 3 + 0], l1 = d5[b * 3 + 1], l2 = d5[b * 3 + 2];
        float m = fmaxf(l0, fmaxf(l1, l2));
        float e0 = __expf(l0 - m), e1 = __expf(l1 - m), e2 = __expf(l2 - m);
        float inv = 1.f / (e0 + e1 + e2);
        float o0 = e0 * inv, o1 = e1 * inv, o2 = e2 * inv;
        size_t gb = (size_t)(bg0 + b);
        float *outp = P.out + gb * 3;
        outp[0] = o0; outp[1] = o1; outp[2] = o2;
        float *xp = P.out + (size_t)Bsz * 3 + gb * 13;
        const float *fsrc = P.feature + gb * Tsz * Fsz + 2 * Fsz + 27;
        #pragma unroll
        for (int q = 0; q < 10; ++q) xp[q] = fsrc[q];
        xp[10] = o0; xp[11] = o1; xp[12] = o2;
    }
}

extern "C" void kernel_launch(void *const *d_in, const int *in_sizes, int n_in,
                              void *d_out, int out_size) {
    Params P;
    P.feature = (const float *)d_in[0];
    P.w_m1 = (const float *)d_in[1];  P.b_m1 = (const float *)d_in[2];
    P.w_m2 = (const float *)d_in[3];  P.b_m2 = (const float *)d_in[4];
    P.w_t1 = (const float *)d_in[5];  P.b_t1 = (const float *)d_in[6];
    P.w_t2 = (const float *)d_in[7];  P.b_t2 = (const float *)d_in[8];
    P.w_s1 = (const float *)d_in[9];  P.b_s1 = (const float *)d_in[10];
    P.w_s2 = (const float *)d_in[11]; P.b_s2 = (const float *)d_in[12];
    P.w_lk = (const float *)d_in[13];
    P.w_lr = (const float *)d_in[14];
    P.b_l  = (const float *)d_in[15];
    P.w_p1 = (const float *)d_in[16]; P.b_p1 = (const float *)d_in[17];
    P.w_p2 = (const float *)d_in[18]; P.b_p2 = (const float *)d_in[19];
    P.w_p3 = (const float *)d_in[20]; P.b_p3 = (const float *)d_in[21];
    P.w_p4 = (const float *)d_in[22]; P.b_p4 = (const float *)d_in[23];
    P.w_p5 = (const float *)d_in[24]; P.b_p5 = (const float *)d_in[25];
    P.out = (float *)d_out;

    repack_kernel<<<(4 * FP4 * H + 255) / 256, 256>>>(
        P.w_lk, P.w_lr, P.w_s1, P.w_s2, P.w_p1, P.w_p2);
    lstm_fused_kernel<<<Bsz / TB, NT>>>(P);
}

// round 13
// speedup vs baseline: 1.1260x; 1.0651x over previous
#include <cuda_runtime.h>
#include <math.h>

#define Bsz 4096
#define Tsz 64
#define Fsz 37
#define TB 8          // batch elements per CTA
#define NP 24         // TB * 3 timesteps
#define NT 128        // LSTM kernel threads (one per hidden unit)
#define NTF 256       // front-end kernel threads
#define FDIM 150      // lin width
#define LINP 152      // padded lin stride (608B rows, 16B aligned)
#define FP4 38        // ceil(FDIM/4) quad-f groups (padded with zeros)
#define KP4 32        // H/4 quad-k groups
#define GATES 512
#define H 128

typedef unsigned long long ull;

// ---- global scratch ----
__device__ ulonglong2 g_wk4[4 * FP4 * H];        // LSTM input weights, quad-f
__device__ ulonglong2 g_wr4[4 * KP4 * H];        // LSTM recurrent weights, quad-k
__device__ float g_lin[(Bsz / TB) * NP * LINP];  // 7.5 MB lin scratch

// shared memory layout (floats) — shared by both kernels
#define OFF_FEAT 0        // 24*37 = 888 (aliased by head buffers in LSTM kernel)
#define OFF_T1M1 888      // 24*16 = 384
#define OFF_S1   1272     // 24*32 = 768
#define OFF_LIN  2040     // 3*8*152 = 3648 (byte 8160, 16B aligned)
#define OFF_H    5688     // 8*128 = 1024   (byte 22752, 16B aligned)
#define SMEM_FLOATS 6712  // 26848 bytes

struct Params {
    const float *feature;
    const float *w_m1, *b_m1, *w_m2, *b_m2;
    const float *w_t1, *b_t1, *w_t2, *b_t2;
    const float *w_s1, *b_s1, *w_s2, *b_s2;
    const float *w_lk, *w_lr, *b_l;
    const float *w_p1, *b_p1, *w_p2, *b_p2, *w_p3, *b_p3, *w_p4, *b_p4, *w_p5, *b_p5;
    float *out;
};

__device__ __forceinline__ float lrelu(float x) { return x >= 0.f ? x : 0.2f * x; }
__device__ __forceinline__ float sigm(float x) { return 1.f / (1.f + __expf(-x)); }

__device__ __forceinline__ ull pack2(float lo, float hi) {
    ull v;
    asm("mov.b64 %0, {%1, %2};" : "=l"(v) : "f"(lo), "f"(hi));
    return v;
}
__device__ __forceinline__ void unpack2(float &lo, float &hi, ull v) {
    asm("mov.b64 {%0, %1}, %2;" : "=f"(lo), "=f"(hi) : "l"(v));
}
__device__ __forceinline__ void ffma2(ull &acc, ull a, ull b) {
    asm("fma.rn.f32x2 %0, %1, %2, %0;" : "+l"(acc) : "l"(a), "l"(b));
}

// ---- pre-kernel: repack w_lk/w_lr into quad-f streams ----
__global__ void repack_kernel(const float *__restrict__ wlk,
                              const float *__restrict__ wlr) {
    int i = blockIdx.x * 256 + threadIdx.x;
    if (i < 4 * FP4 * H) {
        int c = i / (FP4 * H), r = i % (FP4 * H);
        int fq = r / H, j = r % H;
        float w[4];
        #pragma unroll
        for (int q = 0; q < 4; ++q) {
            int f = 4 * fq + q;
            w[q] = (f < FDIM) ? wlk[f * GATES + c * H + j] : 0.f;
        }
        g_wk4[i] = make_ulonglong2(pack2(w[0], w[1]), pack2(w[2], w[3]));
    }
    if (i < 4 * KP4 * H) {
        int c = i / (KP4 * H), r = i % (KP4 * H);
        int kq = r / H, j = r % H;
        float w[4];
        #pragma unroll
        for (int q = 0; q < 4; ++q)
            w[q] = wlr[(4 * kq + q) * GATES + c * H + j];
        g_wr4[i] = make_ulonglong2(pack2(w[0], w[1]), pack2(w[2], w[3]));
    }
}

// lin batch-major: [t][b][f], f contiguous, stride LINP. row r = t*TB+b
#define LIDX(t, f, b) (((t) * TB + (b)) * LINP + (f))

// ============================================================================
// Front-end kernel: passes 1-4 at high occupancy, writes lin to g_lin
// ============================================================================
__global__ void __launch_bounds__(NTF) frontend_kernel(Params P) {
    __shared__ __align__(16) float sm[OFF_H];   // feat, t1m1, S1, linB
    const int tid = threadIdx.x;
    const int bg0 = blockIdx.x * TB;

    float *feat = sm + OFF_FEAT;
    float *t1m1 = sm + OFF_T1M1;
    float *S1   = sm + OFF_S1;
    float *linB = sm + OFF_LIN;

    // ---- load feature rows t=0..2 for 8 batch elems; zero lin pad cols ----
    for (int i = tid; i < NP * Fsz; i += NTF) {
        int p = i / Fsz, f = i % Fsz;
        int b = p / 3, t = p % 3;
        feat[p * Fsz + f] =
            P.feature[(size_t)(bg0 + b) * Tsz * Fsz + (size_t)t * Fsz + f];
    }
    if (tid < NP) {
        linB[tid * LINP + 150] = 0.f;
        linB[tid * LINP + 151] = 0.f;
    }
    __syncthreads();

    // ---- pass1: M1 (q<8) and T1 (q>=8), per (b,t) pair p ----
    for (int i = tid; i < NP * 16; i += NTF) {
        int p = i >> 4, q = i & 15;
        const float *fr = feat + p * Fsz;
        float acc;
        if (q < 8) {
            acc = P.b_m1[q];
            #pragma unroll
            for (int f = 0; f < 3; ++f) acc += fr[33 + f] * P.w_m1[f * 8 + q];
            acc = lrelu(acc);
        } else {
            int j = q - 8;
            acc = P.b_t1[j];
            #pragma unroll
            for (int f = 0; f < Fsz; ++f) acc += fr[f] * P.w_t1[f * 8 + j];
            acc = lrelu(acc);
            acc = fabsf(acc);
        }
        t1m1[i] = acc;
    }
    __syncthreads();

    // ---- pass2: M -> lin[0:16], Tsk -> lin[16:32], Psk -> lin[32:48] ----
    for (int i = tid; i < NP * 32; i += NTF) {
        int p = i >> 5, q = i & 31;
        int b = p / 3, t = p % 3;
        if (q < 16) {
            float acc = P.b_m2[q];
            #pragma unroll
            for (int k = 0; k < 8; ++k) acc += t1m1[p * 16 + k] * P.w_m2[k * 16 + q];
            linB[LIDX(t, q, b)] = lrelu(acc);
        } else {
            int j = q - 16;
            float acc = P.b_t2[j];
            #pragma unroll
            for (int k = 0; k < 8; ++k) acc += t1m1[p * 16 + 8 + k] * P.w_t2[k * 16 + j];
            float v = (acc >= 0.f) ? acc : -0.2f * acc;  // abs(lrelu)
            linB[LIDX(t, 16 + j, b)] = v;
            linB[LIDX(t, 32 + j, b)] = log1pf(v);
        }
    }
    // Pa -> lin[48], feature copy -> lin[113:150]
    for (int i = tid; i < NP * 38; i += NTF) {
        int p = i / 38, q = i % 38;
        int b = p / 3, t = p % 3;
        if (q == 0) linB[LIDX(t, 48, b)] = log1pf(feat[p * Fsz + 31]);
        else        linB[LIDX(t, 113 + (q - 1), b)] = feat[p * Fsz + (q - 1)];
    }
    __syncthreads();

    // ---- pass3: S1 = lrelu(s_in @ w_s1 + b_s1) ----
    for (int i = tid; i < NP * 32; i += NTF) {
        int p = i >> 5, j = i & 31;
        int b = p / 3, t = p % 3;
        float acc = P.b_s1[j];
        for (int f = 0; f < 49; ++f) acc += linB[LIDX(t, f, b)] * P.w_s1[f * 32 + j];
        const float *fr = feat + p * Fsz;
        #pragma unroll
        for (int e = 0; e < 6; ++e) acc += fr[27 + e] * P.w_s1[(49 + e) * 32 + j];
        #pragma unroll
        for (int e = 0; e < 3; ++e) acc += fr[33 + e] * P.w_s1[(55 + e) * 32 + j];
        S1[p * 32 + j] = lrelu(acc);
    }
    __syncthreads();

    // ---- pass4: S -> lin[49:113] ----
    for (int i = tid; i < NP * 64; i += NTF) {
        int p = i >> 6, j = i & 63;
        int b = p / 3, t = p % 3;
        float acc = P.b_s2[j];
        #pragma unroll
        for (int k = 0; k < 32; ++k) acc += S1[p * 32 + k] * P.w_s2[k * 64 + j];
        linB[LIDX(t, 49 + j, b)] = lrelu(acc);
    }
    __syncthreads();

    // ---- copy lin to global scratch (coalesced float4) ----
    float *dst = g_lin + (size_t)blockIdx.x * (NP * LINP);
    for (int i = tid; i < NP * LINP / 4; i += NTF)
        ((float4 *)dst)[i] = ((const float4 *)linB)[i];
}

// ============================================================================
// LSTM + head kernel (R8 core verbatim; lin loaded from g_lin)
// ============================================================================
__global__ void __launch_bounds__(NT, 4) lstm_fused_kernel(Params P) {
    __shared__ __align__(16) float sm[SMEM_FLOATS];
    const int tid = threadIdx.x;
    const int bg0 = blockIdx.x * TB;

    float *linB = sm + OFF_LIN;
    float *hB   = sm + OFF_H;     // [b][k], rows 512B

    // ---- load lin slice from global scratch ----
    {
        const float4 *src =
            (const float4 *)(g_lin + (size_t)blockIdx.x * (NP * LINP));
        for (int i = tid; i < NP * LINP / 4; i += NT)
            ((float4 *)linB)[i] = src[i];
    }
    __syncthreads();

    // ---- LSTM: 3 timesteps (R8 core) ----
    {
        const int j = tid;
        const ulonglong2 *wk0 = g_wk4 + 0 * FP4 * H + j;
        const ulonglong2 *wk1 = g_wk4 + 1 * FP4 * H + j;
        const ulonglong2 *wk2 = g_wk4 + 2 * FP4 * H + j;
        const ulonglong2 *wk3 = g_wk4 + 3 * FP4 * H + j;
        const ulonglong2 *wr0 = g_wr4 + 0 * KP4 * H + j;
        const ulonglong2 *wr1 = g_wr4 + 1 * KP4 * H + j;
        const ulonglong2 *wr2 = g_wr4 + 2 * KP4 * H + j;
        const ulonglong2 *wr3 = g_wr4 + 3 * KP4 * H + j;
        const float bi0 = P.b_l[j], bi1 = P.b_l[j + H];
        const float bi2 = P.b_l[j + 2 * H], bi3 = P.b_l[j + 3 * H];
        float cres[TB];
        #pragma unroll
        for (int b = 0; b < TB; ++b) cres[b] = 0.f;

        for (int t = 0; t < 3; ++t) {
            ull acc0[TB], acc1[TB], acc2[TB], acc3[TB];
            #pragma unroll
            for (int b = 0; b < TB; ++b) {
                acc0[b] = pack2(bi0, 0.f);
                acc1[b] = pack2(bi1, 0.f);
                acc2[b] = pack2(bi2, 0.f);
                acc3[b] = pack2(bi3, 0.f);
            }

            // input GEMM: z += lin_t @ w_lk   (38 quad-f groups)
            #pragma unroll 2
            for (int fq = 0; fq < FP4; ++fq) {
                ulonglong2 w0 = __ldg(wk0 + fq * H);
                ulonglong2 w1 = __ldg(wk1 + fq * H);
                ulonglong2 w2 = __ldg(wk2 + fq * H);
                ulonglong2 w3 = __ldg(wk3 + fq * H);
                ulonglong2 a[TB];
                #pragma unroll
                for (int b = 0; b < TB; ++b)
                    a[b] = *(const ulonglong2 *)(linB + LIDX(t, 4 * fq, b));
                #pragma unroll
                for (int b = 0; b < TB; ++b) {
                    ffma2(acc0[b], a[b].x, w0.x);
                    ffma2(acc1[b], a[b].x, w1.x);
                    ffma2(acc2[b], a[b].x, w2.x);
                    ffma2(acc3[b], a[b].x, w3.x);
                }
                #pragma unroll
                for (int b = 0; b < TB; ++b) {
                    ffma2(acc0[b], a[b].y, w0.y);
                    ffma2(acc1[b], a[b].y, w1.y);
                    ffma2(acc2[b], a[b].y, w2.y);
                    ffma2(acc3[b], a[b].y, w3.y);
                }
            }
            // recurrent GEMM: z += h @ w_lr   (32 quad-k groups; h==0 at t=0)
            if (t > 0) {
                #pragma unroll 2
                for (int kq = 0; kq < KP4; ++kq) {
                    ulonglong2 w0 = __ldg(wr0 + kq * H);
                    ulonglong2 w1 = __ldg(wr1 + kq * H);
                    ulonglong2 w2 = __ldg(wr2 + kq * H);
                    ulonglong2 w3 = __ldg(wr3 + kq * H);
                    ulonglong2 a[TB];
                    #pragma unroll
                    for (int b = 0; b < TB; ++b)
                        a[b] = *(const ulonglong2 *)(hB + b * H + 4 * kq);
                    #pragma unroll
                    for (int b = 0; b < TB; ++b) {
                        ffma2(acc0[b], a[b].x, w0.x);
                        ffma2(acc1[b], a[b].x, w1.x);
                        ffma2(acc2[b], a[b].x, w2.x);
                        ffma2(acc3[b], a[b].x, w3.x);
                    }
                    #pragma unroll
                    for (int b = 0; b < TB; ++b) {
                        ffma2(acc0[b], a[b].y, w0.y);
                        ffma2(acc1[b], a[b].y, w1.y);
                        ffma2(acc2[b], a[b].y, w2.y);
                        ffma2(acc3[b], a[b].y, w3.y);
                    }
                }
            }

            // all reads of hB (this t) must finish before overwrite
            __syncthreads();

            // lane-add + gates + state update, fully in registers
            #pragma unroll
            for (int b = 0; b < TB; ++b) {
                float zi_l, zi_h, zf_l, zf_h, zg_l, zg_h, zo_l, zo_h;
                unpack2(zi_l, zi_h, acc0[b]);
                unpack2(zf_l, zf_h, acc1[b]);
                unpack2(zg_l, zg_h, acc2[b]);
                unpack2(zo_l, zo_h, acc3[b]);
                float zi = zi_l + zi_h, zf = zf_l + zf_h;
                float zg = zg_l + zg_h, zo = zo_l + zo_h;
                float cv = sigm(zf) * cres[b] + sigm(zi) * lrelu(zg);
                cres[b] = cv;
                hB[b * H + j] = sigm(zo) * lrelu(cv);
            }
            __syncthreads();
        }
    }

    // ---- head at t=2 (buffers alias dead smem region [0, 2040)) ----
    float *d1 = sm;        // 8*64 = 512
    float *d2 = sm + 512;  // 8*32
    float *d3 = sm + 768;  // 8*16
    float *d4 = sm + 896;  // 8*8
    float *d5 = sm + 960;  // 8*3

    for (int i = tid; i < TB * 64; i += NT) {
        int b = i >> 6, j = i & 63;
        float acc = P.b_p1[j];
        for (int k = 0; k < H; ++k) acc += hB[b * H + k] * P.w_p1[k * 64 + j];
        d1[i] = lrelu(acc);
    }
    __syncthreads();
    for (int i = tid; i < TB * 32; i += NT) {
        int b = i >> 5, j = i & 31;
        float acc = P.b_p2[j];
        #pragma unroll
        for (int k = 0; k < 64; ++k) acc += d1[b * 64 + k] * P.w_p2[k * 32 + j];
        d2[i] = lrelu(acc);
    }
    __syncthreads();
    for (int i = tid; i < TB * 16; i += NT) {
        int b = i >> 4, j = i & 15;
        float acc = P.b_p3[j];
        #pragma unroll
        for (int k = 0; k < 32; ++k) acc += d2[b * 32 + k] * P.w_p3[k * 16 + j];
        d3[i] = lrelu(acc);
    }
    __syncthreads();
    for (int i = tid; i < TB * 8; i += NT) {
        int b = i >> 3, j = i & 7;
        float acc = P.b_p4[j];
        #pragma unroll
        for (int k = 0; k < 16; ++k) acc += d3[b * 16 + k] * P.w_p4[k * 8 + j];
        d4[i] = lrelu(acc);
    }
    __syncthreads();
    for (int i = tid; i < TB * 3; i += NT) {
        int b = i / 3, j = i % 3;
        float acc = P.b_p5[j];
        #pragma unroll
        for (int k = 0; k < 8; ++k) acc += d4[b * 8 + k] * P.w_p5[k * 3 + j];
        d5[i] = lrelu(acc);
    }
    __syncthreads();

    // ---- softmax + write both outputs ----
    if (tid < TB) {
        int b = tid;
        float l0 = d5[b * 3 + 0], l1 = d5[b * 3 + 1], l2 = d5[b * 3 + 2];
        float m = fmaxf(l0, fmaxf(l1, l2));
        float e0 = __expf(l0 - m), e1 = __expf(l1 - m), e2 = __expf(l2 - m);
        float inv = 1.f / (e0 + e1 + e2);
        float o0 = e0 * inv, o1 = e1 * inv, o2 = e2 * inv;
        size_t gb = (size_t)(bg0 + b);
        float *outp = P.out + gb * 3;
        outp[0] = o0; outp[1] = o1; outp[2] = o2;
        float *xp = P.out + (size_t)Bsz * 3 + gb * 13;
        const float *fsrc = P.feature + gb * Tsz * Fsz + 2 * Fsz + 27;
        #pragma unroll
        for (int q = 0; q < 10; ++q) xp[q] = fsrc[q];
        xp[10] = o0; xp[11] = o1; xp[12] = o2;
    }
}

extern "C" void kernel_launch(void *const *d_in, const int *in_sizes, int n_in,
                              void *d_out, int out_size) {
    Params P;
    P.feature = (const float *)d_in[0];
    P.w_m1 = (const float *)d_in[1];  P.b_m1 = (const float *)d_in[2];
    P.w_m2 = (const float *)d_in[3];  P.b_m2 = (const float *)d_in[4];
    P.w_t1 = (const float *)d_in[5];  P.b_t1 = (const float *)d_in[6];
    P.w_t2 = (const float *)d_in[7];  P.b_t2 = (const float *)d_in[8];
    P.w_s1 = (const float *)d_in[9];  P.b_s1 = (const float *)d_in[10];
    P.w_s2 = (const float *)d_in[11]; P.b_s2 = (const float *)d_in[12];
    P.w_lk = (const float *)d_in[13];
    P.w_lr = (const float *)d_in[14];
    P.b_l  = (const float *)d_in[15];
    P.w_p1 = (const float *)d_in[16]; P.b_p1 = (const float *)d_in[17];
    P.w_p2 = (const float *)d_in[18]; P.b_p2 = (const float *)d_in[19];
    P.w_p3 = (const float *)d_in[20]; P.b_p3 = (const float *)d_in[21];
    P.w_p4 = (const float *)d_in[22]; P.b_p4 = (const float *)d_in[23];
    P.w_p5 = (const float *)d_in[24]; P.b_p5 = (const float *)d_in[25];
    P.out = (float *)d_out;

    repack_kernel<<<(4 * FP4 * H + 255) / 256, 256>>>(P.w_lk, P.w_lr);
    frontend_kernel<<<Bsz / TB, NTF>>>(P);
    lstm_fused_kernel<<<Bsz / TB, NT>>>(P);
}